// round 3
// baseline (speedup 1.0000x reference)
#include <cuda_runtime.h>
#include <cuda_fp16.h>
#include <cstdint>

// BTT dims: x (4096 x 4096), n=m=64, b=a=64, rank=8
// inner[B][n][m][r] = sum_b x[B, n*64+b] * R[n, b, m*8+r]
// out[B, m*64+a]    = sum_{n,r} inner[B][n][m][r] * L[m, n*8+r, a] + bias

#define BTOT 4096

// ---------------- scratch (device globals; no allocation allowed) ----------
__device__ __half g_xh[(size_t)BTOT * 4096];            //  32 MB  x in fp16
__device__ __half g_w1t[(size_t)64 * 512 * 64];         //   4 MB  R^T: [n][j][b], j=m*8+r
__device__ __half g_w2t[(size_t)64 * 64 * 512];         //   4 MB  L^T: [m][a][k], k=n*8+r
__device__ __half g_inner[(size_t)BTOT * 64 * 64 * 8];  // 256 MB  [B][n][m][r]

// ---------------- conversion kernels ---------------------------------------
__global__ void conv_x(const float* __restrict__ x) {
    size_t i = (size_t)blockIdx.x * 256 + threadIdx.x;   // 4194304 threads, 4 elems each
    float4 v = ((const float4*)x)[i];
    __half2 h0 = __floats2half2_rn(v.x, v.y);
    __half2 h1 = __floats2half2_rn(v.z, v.w);
    uint2 u;
    u.x = *(unsigned*)&h0;
    u.y = *(unsigned*)&h1;
    *(uint2*)(g_xh + 4 * i) = u;
}

__global__ void conv_w1(const float* __restrict__ r) {
    int o = blockIdx.x * 256 + threadIdx.x;              // 2097152
    int b = o & 63, j = (o >> 6) & 511, n = o >> 15;
    g_w1t[o] = __float2half_rn(r[(size_t)(n * 64 + b) * 512 + j]);
}

__global__ void conv_w2(const float* __restrict__ l) {
    int o = blockIdx.x * 256 + threadIdx.x;              // 2097152
    int k = o & 511, a = (o >> 9) & 63, m = o >> 15;
    g_w2t[o] = __float2half_rn(l[(size_t)(m * 512 + k) * 64 + a]);
}

// ---------------- mma helper ------------------------------------------------
__device__ __forceinline__ void mma16816(float* c, const unsigned* a, const unsigned* b) {
    asm volatile(
        "mma.sync.aligned.m16n8k16.row.col.f32.f16.f16.f32 "
        "{%0,%1,%2,%3}, {%4,%5,%6,%7}, {%8,%9}, {%0,%1,%2,%3};\n"
        : "+f"(c[0]), "+f"(c[1]), "+f"(c[2]), "+f"(c[3])
        : "r"(a[0]), "r"(a[1]), "r"(a[2]), "r"(a[3]), "r"(b[0]), "r"(b[1]));
}

// ---------------- pass 1: inner = X @ R (per n block) ----------------------
// CTA: (jchunk 0..3, n 0..63, Btile 0..31). Tile 128(M) x 128(J), K=64 single shot.
__global__ __launch_bounds__(256) void btt_pass1() {
    __shared__ __half As[128][72];   // X tile rows x b   (pad 72: conflict-free frags)
    __shared__ __half Bs[128][72];   // R^T  j    x b

    const int jc = blockIdx.x;
    const int n  = blockIdx.y;
    const int bt = blockIdx.z;
    const int tid = threadIdx.x;

#pragma unroll
    for (int i = 0; i < 4; i++) {
        int q = tid + i * 256;          // 0..1023
        int row = q >> 3, c8 = q & 7;   // 128 rows x 8 uint4
        uint4 va = *(const uint4*)(g_xh + (size_t)(bt * 128 + row) * 4096 + n * 64 + c8 * 8);
        *(uint4*)(&As[row][c8 * 8]) = va;
        uint4 vb = *(const uint4*)(g_w1t + (size_t)(n * 512 + jc * 128 + row) * 64 + c8 * 8);
        *(uint4*)(&Bs[row][c8 * 8]) = vb;
    }
    __syncthreads();

    const int warp = tid >> 5, lane = tid & 31;
    const int wm = warp >> 2, wn = warp & 3;   // 2 x 4 warp grid, warp tile 64x32
    const int g = lane >> 2, t = lane & 3;

    float acc[4][4][4];
#pragma unroll
    for (int mf = 0; mf < 4; mf++)
#pragma unroll
        for (int nf = 0; nf < 4; nf++)
#pragma unroll
            for (int c = 0; c < 4; c++) acc[mf][nf][c] = 0.f;

#pragma unroll
    for (int ks = 0; ks < 4; ks++) {
        const int k0 = ks * 16;
        unsigned af[4][4];
#pragma unroll
        for (int mf = 0; mf < 4; mf++) {
            int r0 = wm * 64 + mf * 16 + g;
            af[mf][0] = *(const unsigned*)(&As[r0][k0 + 2 * t]);
            af[mf][1] = *(const unsigned*)(&As[r0 + 8][k0 + 2 * t]);
            af[mf][2] = *(const unsigned*)(&As[r0][k0 + 8 + 2 * t]);
            af[mf][3] = *(const unsigned*)(&As[r0 + 8][k0 + 8 + 2 * t]);
        }
        unsigned bf[4][2];
#pragma unroll
        for (int nf = 0; nf < 4; nf++) {
            int c0 = wn * 32 + nf * 8 + g;
            bf[nf][0] = *(const unsigned*)(&Bs[c0][k0 + 2 * t]);
            bf[nf][1] = *(const unsigned*)(&Bs[c0][k0 + 8 + 2 * t]);
        }
#pragma unroll
        for (int mf = 0; mf < 4; mf++)
#pragma unroll
            for (int nf = 0; nf < 4; nf++) mma16816(acc[mf][nf], af[mf], bf[nf]);
    }

    // epilogue: fp16 store to g_inner[B][n][j] (j = m*8+r contiguous)
#pragma unroll
    for (int mf = 0; mf < 4; mf++) {
        int grow = bt * 128 + wm * 64 + mf * 16 + g;
#pragma unroll
        for (int nf = 0; nf < 4; nf++) {
            int jg = jc * 128 + wn * 32 + nf * 8 + 2 * t;
            size_t base = ((size_t)grow * 64 + n) * 512 + jg;
            __half2 h0 = __floats2half2_rn(acc[mf][nf][0], acc[mf][nf][1]);
            *(__half2*)(g_inner + base) = h0;
            __half2 h1 = __floats2half2_rn(acc[mf][nf][2], acc[mf][nf][3]);
            *(__half2*)(g_inner + base + (size_t)8 * 64 * 512) = h1;   // row +8
        }
    }
}

// ---------------- pass 2: out = inner @ L (per m, 4 m per CTA) -------------
// CTA: (mquad 0..15, Btile 0..63). Out tile 64 x 256 (4 m x 64 a). K=512 in 16 chunks of 32.
__global__ __launch_bounds__(256) void btt_pass2(const float* __restrict__ bias,
                                                 float* __restrict__ out) {
    __shared__ __half As[4][64][40];  // per-m: rows x k_local (pad 40)
    __shared__ __half Bs[4][64][40];  // per-m: a    x k_local

    const int mq = blockIdx.x;
    const int bt = blockIdx.y;
    const int tid = threadIdx.x;
    const int warp = tid >> 5, lane = tid & 31;
    const int wm = warp >> 2, wn = warp & 3;  // warp tile 32 rows x 64 cols (one m = wn)
    const int g = lane >> 2, t = lane & 3;

    float acc[2][8][4];
#pragma unroll
    for (int mf = 0; mf < 2; mf++)
#pragma unroll
        for (int nf = 0; nf < 8; nf++)
#pragma unroll
            for (int c = 0; c < 4; c++) acc[mf][nf][c] = 0.f;

    for (int kc = 0; kc < 16; kc++) {   // 32 k (4 n) per chunk
        __syncthreads();
#pragma unroll
        for (int i = 0; i < 4; i++) {
            int q = tid + i * 256;      // 0..1023
            {   // A: inner[(bt*64+row)][n=kc*4+nl][m=mq*4+mi][r0..7] -> 16B
                int row = q >> 4, nl = (q >> 2) & 3, mi = q & 3;
                size_t u4 = ((size_t)(bt * 64 + row) * 64 + kc * 4 + nl) * 64 + mq * 4 + mi;
                uint4 v = *(const uint4*)(g_inner + u4 * 8);
                *(uint4*)(&As[mi][row][nl * 8]) = v;
            }
            {   // B: w2t[(mq*4+mi)*64+a][k = kc*32 + kl*8 ..] -> 16B
                int mi = q >> 8, a = (q >> 2) & 63, kl = q & 3;
                size_t u4 = ((size_t)(mq * 4 + mi) * 64 + a) * 64 + kc * 4 + kl;
                uint4 v = *(const uint4*)(g_w2t + u4 * 8);
                *(uint4*)(&Bs[mi][a][kl * 8]) = v;
            }
        }
        __syncthreads();

#pragma unroll
        for (int ks = 0; ks < 2; ks++) {
            const int k0 = ks * 16;
            unsigned af[2][4];
#pragma unroll
            for (int mf = 0; mf < 2; mf++) {
                int r0 = wm * 32 + mf * 16 + g;
                af[mf][0] = *(const unsigned*)(&As[wn][r0][k0 + 2 * t]);
                af[mf][1] = *(const unsigned*)(&As[wn][r0 + 8][k0 + 2 * t]);
                af[mf][2] = *(const unsigned*)(&As[wn][r0][k0 + 8 + 2 * t]);
                af[mf][3] = *(const unsigned*)(&As[wn][r0 + 8][k0 + 8 + 2 * t]);
            }
            unsigned bf[8][2];
#pragma unroll
            for (int nf = 0; nf < 8; nf++) {
                int a0 = nf * 8 + g;
                bf[nf][0] = *(const unsigned*)(&Bs[wn][a0][k0 + 2 * t]);
                bf[nf][1] = *(const unsigned*)(&Bs[wn][a0][k0 + 8 + 2 * t]);
            }
#pragma unroll
            for (int mf = 0; mf < 2; mf++)
#pragma unroll
                for (int nf = 0; nf < 8; nf++) mma16816(acc[mf][nf], af[mf], bf[nf]);
        }
    }

    // epilogue: fp32 out + bias
#pragma unroll
    for (int mf = 0; mf < 2; mf++) {
        int row = bt * 64 + wm * 32 + mf * 16 + g;
#pragma unroll
        for (int nf = 0; nf < 8; nf++) {
            int col = (mq * 4 + wn) * 64 + nf * 8 + 2 * t;
            float b0 = bias[col], b1 = bias[col + 1];
            float2 v0 = make_float2(acc[mf][nf][0] + b0, acc[mf][nf][1] + b1);
            *(float2*)(out + (size_t)row * 4096 + col) = v0;
            float2 v1 = make_float2(acc[mf][nf][2] + b0, acc[mf][nf][3] + b1);
            *(float2*)(out + (size_t)(row + 8) * 4096 + col) = v1;
        }
    }
}

// ---------------- launch ----------------------------------------------------
extern "C" void kernel_launch(void* const* d_in, const int* in_sizes, int n_in,
                              void* d_out, int out_size) {
    const float* x    = (const float*)d_in[0];  // (4,1024,4096)
    const float* rw   = (const float*)d_in[1];  // (64,64,512)
    const float* lw   = (const float*)d_in[2];  // (64,512,64)
    const float* bias = (const float*)d_in[3];  // (4096)
    float* out = (float*)d_out;

    conv_x<<<16384, 256>>>(x);
    conv_w1<<<8192, 256>>>(rw);
    conv_w2<<<8192, 256>>>(lw);
    btt_pass1<<<dim3(4, 64, 32), 256>>>();
    btt_pass2<<<dim3(16, 64), 256>>>(bias, out);
}

// round 5
// speedup vs baseline: 1.0260x; 1.0260x over previous
#include <cuda_runtime.h>
#include <cuda_fp16.h>
#include <cstdint>

// BTT dims: x (4096 x 4096), n=m=64, b=a=64, rank=8
// inner[B][n][m][r] = sum_b x[B, n*64+b] * R[n, b, m*8+r]
// out[B, m*64+a]    = sum_{n,r} inner[B][n][m][r] * L[m, n*8+r, a] + bias
// Chunked over B (4 x 1024 rows) so the inner tensor stays L2-resident.

#define BTOT 4096
#define CHUNK 1024
#define NCHUNK 4

// ---------------- scratch (device globals; no allocation allowed) ----------
__device__ __half g_xh[(size_t)BTOT * 4096];             //  32 MB  x in fp16
__device__ __half g_w1t[(size_t)64 * 512 * 64];          //   4 MB  R^T: [n][j][b], j=m*8+r
__device__ __half g_w2t[(size_t)64 * 64 * 512];          //   4 MB  L^T: [m][a][k], k=n*8+r
__device__ __half g_inner[(size_t)CHUNK * 64 * 64 * 8];  //  64 MB  [Blocal][n][m][r] (reused per chunk)

// ---------------- conversion kernels ---------------------------------------
__global__ void conv_x(const float* __restrict__ x) {
    size_t i = (size_t)blockIdx.x * 256 + threadIdx.x;
    float4 v = ((const float4*)x)[i];
    __half2 h0 = __floats2half2_rn(v.x, v.y);
    __half2 h1 = __floats2half2_rn(v.z, v.w);
    uint2 u;
    u.x = *(unsigned*)&h0;
    u.y = *(unsigned*)&h1;
    *(uint2*)(g_xh + 4 * i) = u;
}

__global__ void conv_w1(const float* __restrict__ r) {
    int o = blockIdx.x * 256 + threadIdx.x;
    int b = o & 63, j = (o >> 6) & 511, n = o >> 15;
    g_w1t[o] = __float2half_rn(r[(size_t)(n * 64 + b) * 512 + j]);
}

__global__ void conv_w2(const float* __restrict__ l) {
    int o = blockIdx.x * 256 + threadIdx.x;
    int k = o & 511, a = (o >> 9) & 63, m = o >> 15;
    g_w2t[o] = __float2half_rn(l[(size_t)(m * 512 + k) * 64 + a]);
}

// ---------------- asm helpers ----------------------------------------------
__device__ __forceinline__ void mma16816(float* c, const unsigned* a, const unsigned* b) {
    asm volatile(
        "mma.sync.aligned.m16n8k16.row.col.f32.f16.f16.f32 "
        "{%0,%1,%2,%3}, {%4,%5,%6,%7}, {%8,%9}, {%0,%1,%2,%3};\n"
        : "+f"(c[0]), "+f"(c[1]), "+f"(c[2]), "+f"(c[3])
        : "r"(a[0]), "r"(a[1]), "r"(a[2]), "r"(a[3]), "r"(b[0]), "r"(b[1]));
}

__device__ __forceinline__ void ldsm4(unsigned& r0, unsigned& r1, unsigned& r2, unsigned& r3,
                                      unsigned addr) {
    asm volatile("ldmatrix.sync.aligned.m8n8.x4.shared.b16 {%0,%1,%2,%3}, [%4];"
                 : "=r"(r0), "=r"(r1), "=r"(r2), "=r"(r3) : "r"(addr));
}

__device__ __forceinline__ void cpa16(unsigned dst, const void* src) {
    asm volatile("cp.async.cg.shared.global [%0], [%1], 16;" :: "r"(dst), "l"(src));
}
__device__ __forceinline__ void cpcommit() { asm volatile("cp.async.commit_group;"); }
template <int N> __device__ __forceinline__ void cpwait() {
    asm volatile("cp.async.wait_group %0;" :: "n"(N));
}

// ---------------- pass 1: inner = X @ R (per n block) ----------------------
// CTA: (jchunk 0..3, n 0..63, bt 0..7). Tile 128(Brows) x 128(J), K=64 single shot.
__global__ __launch_bounds__(256) void btt_pass1(int chunk) {
    __shared__ __half As[128][72];   // X tile rows x b (stride 144B: 16B-aligned, ldsm conflict-free)
    __shared__ __half Bs[128][72];   // R^T  j    x b

    const int jc = blockIdx.x;
    const int n  = blockIdx.y;
    const int bt = blockIdx.z;
    const int tid = threadIdx.x;
    const int grow0 = chunk * CHUNK + bt * 128;

    unsigned sA = (unsigned)__cvta_generic_to_shared(&As[0][0]);
    unsigned sB = (unsigned)__cvta_generic_to_shared(&Bs[0][0]);

#pragma unroll
    for (int i = 0; i < 4; i++) {
        int q = tid + i * 256;          // 0..1023
        int row = q >> 3, c8 = q & 7;   // 128 rows x 8 x 16B
        cpa16(sA + (row * 72 + c8 * 8) * 2,
              g_xh + (size_t)(grow0 + row) * 4096 + n * 64 + c8 * 8);
        cpa16(sB + (row * 72 + c8 * 8) * 2,
              g_w1t + (size_t)(n * 512 + jc * 128 + row) * 64 + c8 * 8);
    }
    cpcommit();
    cpwait<0>();
    __syncthreads();

    const int warp = tid >> 5, lane = tid & 31;
    const int wm = warp >> 2, wn = warp & 3;   // 2 x 4 warp grid, warp tile 64x32
    const int g = lane >> 2, t = lane & 3;
    const int rl = lane & 7, sel = lane >> 3;
    // ldmatrix per-lane offsets (in bytes), row stride 72 halves
    const int offA = ((rl + (sel & 1) * 8) * 72 + (sel >> 1) * 8) * 2;
    const int offB = (((sel >> 1) * 8 + rl) * 72 + (sel & 1) * 8) * 2;

    float acc[4][4][4];
#pragma unroll
    for (int mf = 0; mf < 4; mf++)
#pragma unroll
        for (int nf = 0; nf < 4; nf++)
#pragma unroll
            for (int c = 0; c < 4; c++) acc[mf][nf][c] = 0.f;

#pragma unroll
    for (int ks = 0; ks < 4; ks++) {
        const int k0 = ks * 16;
        unsigned af[4][4], bf[4][2];
#pragma unroll
        for (int mf = 0; mf < 4; mf++)
            ldsm4(af[mf][0], af[mf][1], af[mf][2], af[mf][3],
                  sA + ((wm * 64 + mf * 16) * 72 + k0) * 2 + offA);
#pragma unroll
        for (int p = 0; p < 2; p++)
            ldsm4(bf[2 * p][0], bf[2 * p][1], bf[2 * p + 1][0], bf[2 * p + 1][1],
                  sB + ((wn * 32 + p * 16) * 72 + k0) * 2 + offB);
#pragma unroll
        for (int mf = 0; mf < 4; mf++)
#pragma unroll
            for (int nf = 0; nf < 4; nf++) mma16816(acc[mf][nf], af[mf], bf[nf]);
    }

    // epilogue: fp16 store to g_inner[Blocal][n][j] (j = m*8+r contiguous)
#pragma unroll
    for (int mf = 0; mf < 4; mf++) {
        int lrow = bt * 128 + wm * 64 + mf * 16 + g;
#pragma unroll
        for (int nf = 0; nf < 4; nf++) {
            int jg = jc * 128 + wn * 32 + nf * 8 + 2 * t;
            size_t base = ((size_t)lrow * 64 + n) * 512 + jg;
            __half2 h0 = __floats2half2_rn(acc[mf][nf][0], acc[mf][nf][1]);
            *(__half2*)(g_inner + base) = h0;
            __half2 h1 = __floats2half2_rn(acc[mf][nf][2], acc[mf][nf][3]);
            *(__half2*)(g_inner + base + (size_t)8 * 64 * 512) = h1;   // row +8
        }
    }
}

// ---------------- pass 2: out = inner @ L (4 m per CTA) --------------------
// CTA: (mq 0..15, bt 0..15). Out tile 64 x 256. K=512 in 16 chunks of 32,
// 2-stage cp.async double buffer. Dynamic smem 81920 B.
// Layout (halves): A[s][mi][row][40] at s*10240 + (mi*64+row)*40
//                  B[s][mi][a][40]   at 20480 + s*10240 + (mi*64+a)*40
#define P2_ASTG 10240
#define P2_BOFF 20480

__device__ __forceinline__ void p2_load(unsigned sbase, int s, int kc, int bt, int mq, int tid) {
#pragma unroll
    for (int i = 0; i < 4; i++) {
        int q = tid + i * 256;          // 0..1023
        int row = q >> 4, nl = (q >> 2) & 3, mi = q & 3;
        cpa16(sbase + (s * P2_ASTG + (mi * 64 + row) * 40 + nl * 8) * 2,
              g_inner + (((size_t)(bt * 64 + row) * 64 + kc * 4 + nl) * 64 + mq * 4 + mi) * 8);
    }
#pragma unroll
    for (int i = 0; i < 4; i++) {
        int q = tid + i * 256;
        int mi = q >> 8, a = (q >> 2) & 63, kl = q & 3;
        cpa16(sbase + (P2_BOFF + s * P2_ASTG + (mi * 64 + a) * 40 + kl * 8) * 2,
              g_w2t + ((size_t)(mq * 4 + mi) * 64 + a) * 512 + kc * 32 + kl * 8);
    }
    cpcommit();
}

__global__ __launch_bounds__(256) void btt_pass2(const float* __restrict__ bias,
                                                 float* __restrict__ out, int chunk) {
    extern __shared__ __half dsm[];
    const int mq = blockIdx.x;
    const int bt = blockIdx.y;
    const int tid = threadIdx.x;
    unsigned sbase = (unsigned)__cvta_generic_to_shared(dsm);

    const int warp = tid >> 5, lane = tid & 31;
    const int wm = warp >> 2, wn = warp & 3;  // warp tile 32 rows x 64 cols (one m = wn)
    const int g = lane >> 2, t = lane & 3;
    const int rl = lane & 7, sel = lane >> 3;
    const int offA = ((rl + (sel & 1) * 8) * 40 + (sel >> 1) * 8) * 2;
    const int offB = (((sel >> 1) * 8 + rl) * 40 + (sel & 1) * 8) * 2;

    float acc[2][8][4];
#pragma unroll
    for (int mf = 0; mf < 2; mf++)
#pragma unroll
        for (int nf = 0; nf < 8; nf++)
#pragma unroll
            for (int c = 0; c < 4; c++) acc[mf][nf][c] = 0.f;

    p2_load(sbase, 0, 0, bt, mq, tid);

    for (int kc = 0; kc < 16; kc++) {
        const int s = kc & 1;
        if (kc + 1 < 16) {
            p2_load(sbase, s ^ 1, kc + 1, bt, mq, tid);  // s^1 free: synced at end of kc-1
            cpwait<1>();                                  // stage s complete
        } else {
            cpwait<0>();
        }
        __syncthreads();

        unsigned aBase = sbase + (s * P2_ASTG + wn * 64 * 40) * 2;
        unsigned bBase = sbase + ((P2_BOFF + s * P2_ASTG) + wn * 64 * 40) * 2;
#pragma unroll
        for (int ks = 0; ks < 2; ks++) {
            const int k0 = ks * 16;
            unsigned af[2][4], bf[8][2];
#pragma unroll
            for (int mf = 0; mf < 2; mf++)
                ldsm4(af[mf][0], af[mf][1], af[mf][2], af[mf][3],
                      aBase + ((wm * 32 + mf * 16) * 40 + k0) * 2 + offA);
#pragma unroll
            for (int p = 0; p < 4; p++)
                ldsm4(bf[2 * p][0], bf[2 * p][1], bf[2 * p + 1][0], bf[2 * p + 1][1],
                      bBase + ((p * 16) * 40 + k0) * 2 + offB);
#pragma unroll
            for (int mf = 0; mf < 2; mf++)
#pragma unroll
                for (int nf = 0; nf < 8; nf++) mma16816(acc[mf][nf], af[mf], bf[nf]);
        }
        __syncthreads();  // all warps done reading stage s before it is refilled
    }

    // epilogue: fp32 out + bias
#pragma unroll
    for (int mf = 0; mf < 2; mf++) {
        int row = chunk * CHUNK + bt * 64 + wm * 32 + mf * 16 + g;
#pragma unroll
        for (int nf = 0; nf < 8; nf++) {
            int col = (mq * 4 + wn) * 64 + nf * 8 + 2 * t;
            float b0 = bias[col], b1 = bias[col + 1];
            float2 v0 = make_float2(acc[mf][nf][0] + b0, acc[mf][nf][1] + b1);
            *(float2*)(out + (size_t)row * 4096 + col) = v0;
            float2 v1 = make_float2(acc[mf][nf][2] + b0, acc[mf][nf][3] + b1);
            *(float2*)(out + (size_t)(row + 8) * 4096 + col) = v1;
        }
    }
}

// ---------------- launch ----------------------------------------------------
extern "C" void kernel_launch(void* const* d_in, const int* in_sizes, int n_in,
                              void* d_out, int out_size) {
    const float* x    = (const float*)d_in[0];  // (4,1024,4096)
    const float* rw   = (const float*)d_in[1];  // (64,64,512)
    const float* lw   = (const float*)d_in[2];  // (64,512,64)
    const float* bias = (const float*)d_in[3];  // (4096)
    float* out = (float*)d_out;

    // 81920 B dynamic smem for pass2 (attribute set persists from first,
    // uncaptured, correctness call)
    cudaFuncSetAttribute(btt_pass2, cudaFuncAttributeMaxDynamicSharedMemorySize, 81920);

    conv_x<<<16384, 256>>>(x);
    conv_w1<<<8192, 256>>>(rw);
    conv_w2<<<8192, 256>>>(lw);
    for (int c = 0; c < NCHUNK; c++) {
        btt_pass1<<<dim3(4, 64, 8), 256>>>(c);
        btt_pass2<<<dim3(16, 16), 256, 81920>>>(bias, out, c);
    }
}